// round 2
// baseline (speedup 1.0000x reference)
#include <cuda_runtime.h>
#include <cuda_bf16.h>
#include <math.h>

// Problem constants
#define VOCAB 50000
#define DIM   512
#define SEQL  512
#define BATCH 256
#define NCLS  20

// ---------------- device scratch (no runtime alloc allowed) ----------------
__device__ float g_embW[(size_t)VOCAB * DIM];     // emb @ Wx + b, ~100 MB
__device__ float g_h[2 * BATCH * DIM];            // ping-pong hidden state
__device__ unsigned g_bar_count = 0;
__device__ unsigned g_bar_gen   = 0;
__device__ unsigned g_done      = 0;

// ---------------- kernel 1: embW = emb @ Wx + b  (fp32 tiled GEMM) ----------
// M=50000, N=512, K=512.  BM=BN=64, BK=16, 256 threads, 4x4 per thread.
__global__ __launch_bounds__(256) void embw_gemm(
    const float* __restrict__ A,    // emb [M][512]
    const float* __restrict__ B,    // Wx  [512][512]
    const float* __restrict__ bias, // b [512]
    int M)
{
    __shared__ float As[16][68];   // transposed A tile [k][m], padded
    __shared__ float Bs[16][64];   // [k][n]

    const int tid  = threadIdx.x;
    const int row0 = blockIdx.y * 64;
    const int col0 = blockIdx.x * 64;

    const int tm = tid >> 4;        // 0..15 (row group of 4)
    const int tn = tid & 15;        // 0..15 (col group of 4)

    // loader indices
    const int am  = tid >> 2;       // 0..63
    const int ak4 = (tid & 3) << 2; // 0,4,8,12
    const int bk  = tid >> 4;       // 0..15
    const int bn4 = (tid & 15) << 2;

    float4 acc0 = {0,0,0,0}, acc1 = {0,0,0,0}, acc2 = {0,0,0,0}, acc3 = {0,0,0,0};

    for (int k0 = 0; k0 < DIM; k0 += 16) {
        float4 av = {0,0,0,0};
        if (row0 + am < M)
            av = *(const float4*)(A + (size_t)(row0 + am) * DIM + k0 + ak4);
        As[ak4 + 0][am] = av.x;
        As[ak4 + 1][am] = av.y;
        As[ak4 + 2][am] = av.z;
        As[ak4 + 3][am] = av.w;

        *(float4*)&Bs[bk][bn4] = *(const float4*)(B + (size_t)(k0 + bk) * DIM + col0 + bn4);
        __syncthreads();

        #pragma unroll
        for (int kk = 0; kk < 16; kk++) {
            float4 a  = *(const float4*)&As[kk][tm * 4];
            float4 bv = *(const float4*)&Bs[kk][tn * 4];
            acc0.x += a.x * bv.x; acc0.y += a.x * bv.y; acc0.z += a.x * bv.z; acc0.w += a.x * bv.w;
            acc1.x += a.y * bv.x; acc1.y += a.y * bv.y; acc1.z += a.y * bv.z; acc1.w += a.y * bv.w;
            acc2.x += a.z * bv.x; acc2.y += a.z * bv.y; acc2.z += a.z * bv.z; acc2.w += a.z * bv.w;
            acc3.x += a.w * bv.x; acc3.y += a.w * bv.y; acc3.z += a.w * bv.z; acc3.w += a.w * bv.w;
        }
        __syncthreads();
    }

    float4 bb = *(const float4*)(bias + col0 + tn * 4);
    float4 outs[4] = {acc0, acc1, acc2, acc3};
    #pragma unroll
    for (int i = 0; i < 4; i++) {
        int row = row0 + tm * 4 + i;
        if (row < M) {
            float4 o;
            o.x = outs[i].x + bb.x;
            o.y = outs[i].y + bb.y;
            o.z = outs[i].z + bb.z;
            o.w = outs[i].w + bb.w;
            *(float4*)(g_embW + (size_t)row * DIM + col0 + tn * 4) = o;
        }
    }
}

// ---------------- grid barrier (all CTAs resident: 128 CTAs, 1/SM) ----------
__device__ __forceinline__ void grid_barrier(unsigned target, unsigned ncta)
{
    __threadfence();
    __syncthreads();
    if (threadIdx.x == 0) {
        unsigned arrived = atomicAdd(&g_bar_count, 1u);
        if (arrived == ncta - 1u) {
            g_bar_count = 0;          // reset BEFORE release
            __threadfence();
            atomicExch(&g_bar_gen, target);
        } else {
            volatile unsigned* gen = &g_bar_gen;
            while (*gen < target) { }
            __threadfence();
        }
    }
    __syncthreads();
}

// ---------------- kernel 2: persistent RNN recurrence -----------------------
// 128 CTAs: blockIdx = rg*8 + cg.  rg in [0,16): 16 batch rows.  cg in [0,8): 64 cols.
// Wh column slice (512 x 64, fp32) resident in SMEM for all 512 steps.
#define RNN_SMEM_BYTES ((512 * 64 + 16 * 512) * 4)   // 160 KB

__global__ __launch_bounds__(256, 1) void rnn_recur(
    const int*   __restrict__ x,    // [256][512] tokens
    const float* __restrict__ Wh)   // [512][512]
{
    extern __shared__ float smem[];
    float* whs = smem;               // [512][64]
    float* h_s = smem + 512 * 64;    // [16][512]

    const int tid  = threadIdx.x;
    const int rg   = blockIdx.x >> 3;
    const int cg   = blockIdx.x & 7;
    const int col0 = cg * 64;
    const int row0 = rg * 16;
    const unsigned ncta = gridDim.x;

    // load Wh slice into SMEM once (coalesced)
    for (int i = tid; i < 512 * 16; i += 256) {
        int d  = i >> 4;
        int j4 = (i & 15) << 2;
        *(float4*)&whs[d * 64 + j4] =
            *(const float4*)(Wh + (size_t)d * DIM + col0 + j4);
    }

    const int r    = tid >> 4;      // local row 0..15
    const int c4   = tid & 15;      // local 4-col block
    const int grow = row0 + r;      // global batch row
    const int* xrow = x + (size_t)grow * SEQL;

    const float4* hrow4 = (const float4*)&h_s[r * 512];
    const float4* w4    = ((const float4*)whs) + c4;   // stride 16 float4 per d

    __syncthreads();

    for (int l = 0; l < SEQL; l++) {
        // issue the xin gather early (independent of barrier / h)
        int token = __ldg(xrow + l);
        float4 xin = __ldg((const float4*)(g_embW + (size_t)token * DIM + col0 + c4 * 4));

        if (l > 0) {
            grid_barrier((unsigned)l, ncta);
            // load previous h rows (contiguous 32KB) via L2 (bypass stale L1)
            const float* hsrc = g_h + (size_t)(l & 1) * (BATCH * DIM) + (size_t)row0 * DIM;
            for (int i = tid * 4; i < 16 * 512; i += 1024)
                *(float4*)&h_s[i] = __ldcg((const float4*)(hsrc + i));
            __syncthreads();
        }

        float4 acc = {0.f, 0.f, 0.f, 0.f};
        if (l > 0) {
            #pragma unroll 4
            for (int d4 = 0; d4 < 128; d4++) {
                float4 hv = hrow4[d4];
                float4 w0 = w4[(d4 * 4 + 0) * 16];
                float4 w1 = w4[(d4 * 4 + 1) * 16];
                float4 w2 = w4[(d4 * 4 + 2) * 16];
                float4 w3 = w4[(d4 * 4 + 3) * 16];
                acc.x += hv.x * w0.x; acc.y += hv.x * w0.y; acc.z += hv.x * w0.z; acc.w += hv.x * w0.w;
                acc.x += hv.y * w1.x; acc.y += hv.y * w1.y; acc.z += hv.y * w1.z; acc.w += hv.y * w1.w;
                acc.x += hv.z * w2.x; acc.y += hv.z * w2.y; acc.z += hv.z * w2.z; acc.w += hv.z * w2.w;
                acc.x += hv.w * w3.x; acc.y += hv.w * w3.y; acc.z += hv.w * w3.z; acc.w += hv.w * w3.w;
            }
        }

        float4 hn;
        hn.x = tanhf(acc.x + xin.x);
        hn.y = tanhf(acc.y + xin.y);
        hn.z = tanhf(acc.z + xin.z);
        hn.w = tanhf(acc.w + xin.w);

        __stcg((float4*)(g_h + (size_t)((l + 1) & 1) * (BATCH * DIM)
                         + (size_t)grow * DIM + col0 + c4 * 4), hn);
    }

    // reset barrier state for next graph replay (no one waits on this)
    __syncthreads();
    if (threadIdx.x == 0) {
        __threadfence();
        unsigned d = atomicAdd(&g_done, 1u);
        if (d == ncta - 1u) {
            g_done = 0;
            g_bar_gen = 0;
            __threadfence();
        }
    }
}

// ---------------- kernel 3: logits + softmax --------------------------------
// final h is in g_h[0] (step 511 writes buffer (511+1)&1 == 0).
__global__ __launch_bounds__(256) void softmax_kernel(
    const float* __restrict__ Wd,   // [512][20]
    const float* __restrict__ bd,   // [20]
    float* __restrict__ out)        // [256][20]
{
    int b    = blockIdx.x * 8 + (threadIdx.x >> 5);
    int lane = threadIdx.x & 31;
    if (b >= BATCH) return;

    const float* h = g_h + (size_t)b * DIM;

    float acc[NCLS];
    #pragma unroll
    for (int c = 0; c < NCLS; c++) acc[c] = 0.f;

    for (int d = lane; d < DIM; d += 32) {
        float hv = h[d];
        #pragma unroll
        for (int c = 0; c < NCLS; c++)
            acc[c] += hv * Wd[d * NCLS + c];
    }
    #pragma unroll
    for (int c = 0; c < NCLS; c++) {
        #pragma unroll
        for (int off = 16; off > 0; off >>= 1)
            acc[c] += __shfl_xor_sync(0xFFFFFFFFu, acc[c], off);
    }
    if (lane == 0) {
        float logit[NCLS];
        float m = -1e30f;
        #pragma unroll
        for (int c = 0; c < NCLS; c++) {
            logit[c] = acc[c] + bd[c];
            m = fmaxf(m, logit[c]);
        }
        float s = 0.f;
        #pragma unroll
        for (int c = 0; c < NCLS; c++) {
            logit[c] = expf(logit[c] - m);
            s += logit[c];
        }
        float inv = 1.0f / s;
        #pragma unroll
        for (int c = 0; c < NCLS; c++)
            out[b * NCLS + c] = logit[c] * inv;
    }
}

// ---------------- launch ----------------------------------------------------
extern "C" void kernel_launch(void* const* d_in, const int* in_sizes, int n_in,
                              void* d_out, int out_size)
{
    const int*   x   = (const int*)  d_in[0];
    const float* emb = (const float*)d_in[1];
    const float* Wx  = (const float*)d_in[2];
    const float* Wh  = (const float*)d_in[3];
    const float* b   = (const float*)d_in[4];
    const float* Wd  = (const float*)d_in[5];
    const float* bd  = (const float*)d_in[6];
    float* out = (float*)d_out;

    // 1) embW = emb @ Wx + b
    embw_gemm<<<dim3(DIM / 64, (VOCAB + 63) / 64), 256>>>(emb, Wx, b, VOCAB);

    // 2) persistent recurrence (128 CTAs, 160KB dynamic smem, all resident)
    cudaFuncSetAttribute(rnn_recur, cudaFuncAttributeMaxDynamicSharedMemorySize,
                         RNN_SMEM_BYTES);
    rnn_recur<<<128, 256, RNN_SMEM_BYTES>>>(x, Wh);

    // 3) logits + softmax
    softmax_kernel<<<(BATCH + 7) / 8, 256>>>(Wd, bd, out);
}

// round 4
// speedup vs baseline: 1.0591x; 1.0591x over previous
#include <cuda_runtime.h>
#include <cuda_bf16.h>
#include <math.h>

// Problem constants
#define VOCAB 50000
#define DIM   512
#define SEQL  512
#define BATCH 256
#define NCLS  20
#define HSTR  516   // padded h_s row stride (floats) to avoid bank conflicts

// ---------------- device scratch (no runtime alloc allowed) ----------------
__device__ float g_embW[(size_t)VOCAB * DIM];       // emb @ Wx + b, ~100 MB
__device__ float g_h[2 * BATCH * DIM];              // ping-pong hidden state
__device__ unsigned g_flags[16][32];                // per-group step flags (8 used, line-padded)

// STRONG acquire/release flag ops (PTX memory model compliant).
// R2 used weak ld.cg/st.cg here -> formally a data race -> rel_err 0.23.
__device__ __forceinline__ unsigned ldflag_acq(const unsigned* p) {
    unsigned v;
    asm volatile("ld.acquire.gpu.global.u32 %0, [%1];" : "=r"(v) : "l"(p) : "memory");
    return v;
}
__device__ __forceinline__ void stflag_rel(unsigned* p, unsigned v) {
    asm volatile("st.release.gpu.global.u32 [%0], %1;" :: "l"(p), "r"(v) : "memory");
}

// ---------------- kernel 1: embW = emb @ Wx + b  (fp32 tiled GEMM) ----------
// M=50000, N=512, K=512.  BM=128, BN=64, BK=16, 256 threads, 8x4 per thread.
__global__ __launch_bounds__(256) void embw_gemm(
    const float* __restrict__ A,    // emb [M][512]
    const float* __restrict__ B,    // Wx  [512][512]
    const float* __restrict__ bias, // b [512]
    int M)
{
    __shared__ float As[16][132];   // transposed A tile [k][m], padded
    __shared__ float Bs[16][64];    // [k][n]

    const int tid  = threadIdx.x;
    const int row0 = blockIdx.y * 128;
    const int col0 = blockIdx.x * 64;

    const int tm = tid >> 4;        // 0..15 -> 8 rows each
    const int tn = tid & 15;        // 0..15 -> 4 cols each

    float4 acc[8];
    #pragma unroll
    for (int i = 0; i < 8; i++) acc[i] = make_float4(0.f, 0.f, 0.f, 0.f);

    const int bkr = tid >> 4;          // B loader row 0..15
    const int bn4 = (tid & 15) << 2;   // B loader col

    for (int k0 = 0; k0 < DIM; k0 += 16) {
        // load A tile (128x16) transposed: 512 float4, 2 per thread
        #pragma unroll
        for (int t = 0; t < 2; t++) {
            int idx = tid + t * 256;
            int am  = idx >> 2;
            int ak4 = (idx & 3) << 2;
            float4 av = make_float4(0.f, 0.f, 0.f, 0.f);
            if (row0 + am < M)
                av = *(const float4*)(A + (size_t)(row0 + am) * DIM + k0 + ak4);
            As[ak4 + 0][am] = av.x;
            As[ak4 + 1][am] = av.y;
            As[ak4 + 2][am] = av.z;
            As[ak4 + 3][am] = av.w;
        }
        // load B tile (16x64): 1 float4 per thread
        *(float4*)&Bs[bkr][bn4] =
            *(const float4*)(B + (size_t)(k0 + bkr) * DIM + col0 + bn4);
        __syncthreads();

        #pragma unroll
        for (int kk = 0; kk < 16; kk++) {
            float4 bv = *(const float4*)&Bs[kk][tn << 2];
            float4 a0 = *(const float4*)&As[kk][tm * 8];
            float4 a1 = *(const float4*)&As[kk][tm * 8 + 4];
            float av[8] = {a0.x, a0.y, a0.z, a0.w, a1.x, a1.y, a1.z, a1.w};
            #pragma unroll
            for (int i = 0; i < 8; i++) {
                acc[i].x += av[i] * bv.x;
                acc[i].y += av[i] * bv.y;
                acc[i].z += av[i] * bv.z;
                acc[i].w += av[i] * bv.w;
            }
        }
        __syncthreads();
    }

    float4 bb = *(const float4*)(bias + col0 + (tn << 2));
    #pragma unroll
    for (int i = 0; i < 8; i++) {
        int row = row0 + tm * 8 + i;
        if (row < M) {
            float4 o;
            o.x = acc[i].x + bb.x;
            o.y = acc[i].y + bb.y;
            o.z = acc[i].z + bb.z;
            o.w = acc[i].w + bb.w;
            *(float4*)(g_embW + (size_t)row * DIM + col0 + (tn << 2)) = o;
        }
    }
}

// ---------------- kernel 2: persistent RNN recurrence -----------------------
// 128 CTAs: blockIdx = rg*8 + cg.  rg in [0,16): 16 batch rows.  cg in [0,8): 64 cols.
// Row-groups are INDEPENDENT: only the 8 CTAs of one rg synchronize (flag protocol).
// Wh column slice (512 x 64, fp32) resident in SMEM for all 512 steps.
#define RNN_SMEM_BYTES ((512 * 64 + 16 * HSTR) * 4)   // ~160.25 KB

__global__ __launch_bounds__(256, 1) void rnn_recur(
    const int*   __restrict__ x,    // [256][512] tokens
    const float* __restrict__ Wh)   // [512][512]
{
    extern __shared__ float smem[];
    float* whs = smem;               // [512][64]
    float* h_s = smem + 512 * 64;    // [16][HSTR]

    const int tid  = threadIdx.x;
    const int warp = tid >> 5;
    const int lane = tid & 31;
    const int bid  = blockIdx.x;
    const int rg   = bid >> 3;
    const int cg   = bid & 7;
    const int col0 = cg * 64;
    const int row0 = rg * 16;

    // load Wh slice into SMEM once (coalesced)
    for (int i = tid; i < 512 * 16; i += 256) {
        int d  = i >> 4;
        int j4 = (i & 15) << 2;
        *(float4*)&whs[d * 64 + j4] =
            *(const float4*)(Wh + (size_t)d * DIM + col0 + j4);
    }

    // warp covers 4 rows x 8 col-groups (halves Wh crossbar traffic)
    const int r    = ((warp & 3) << 2) + (lane >> 3);   // 0..15
    const int c4   = ((warp >> 2) << 3) + (lane & 7);   // 0..15
    const int grow = row0 + r;
    const int* xrow = x + (size_t)grow * SEQL;

    const float4* hrow4 = (const float4*)&h_s[r * HSTR];
    const float4* w4    = ((const float4*)whs) + c4;    // stride 16 float4 per d

    // replay-safe monotonic base (all group members ended last launch equal)
    const unsigned base = ldflag_acq(&g_flags[rg][cg]);
    unsigned* myflag = &g_flags[rg][cg];

    __syncthreads();

    for (int l = 0; l < SEQL; l++) {
        // prefetch xin early (independent of sync / h)
        int token = __ldg(xrow + l);
        float4 xin = __ldg((const float4*)(g_embW + (size_t)token * DIM + col0 + (c4 << 2)));

        float4 acc = make_float4(0.f, 0.f, 0.f, 0.f);

        if (l > 0) {
            // ---- per-group acquire wait (8 producers) ----
            unsigned target = base + (unsigned)l;
            if (lane < 8) {
                const unsigned* f = &g_flags[rg][lane];
                while ((int)(ldflag_acq(f) - target) < 0) { }
            }
            __syncwarp();
            __threadfence();   // bridge acquire to non-polling lanes

            // ---- load 16x512 h block (32KB) from L2, deep MLP ----
            const float* hsrc = g_h + (size_t)(l & 1) * (BATCH * DIM) + (size_t)row0 * DIM;
            float4 hld[8];
            #pragma unroll
            for (int k = 0; k < 8; k++) {
                int idx = tid + (k << 8);
                hld[k] = __ldcg((const float4*)(hsrc + (idx >> 7) * DIM + ((idx & 127) << 2)));
            }
            #pragma unroll
            for (int k = 0; k < 8; k++) {
                int idx = tid + (k << 8);
                *(float4*)&h_s[(idx >> 7) * HSTR + ((idx & 127) << 2)] = hld[k];
            }
            __syncthreads();

            // ---- h @ Wh slice: 2048 FMAs/thread ----
            #pragma unroll 4
            for (int d4 = 0; d4 < 128; d4++) {
                float4 hv = hrow4[d4];
                float4 w0 = w4[(d4 * 4 + 0) * 16];
                float4 w1 = w4[(d4 * 4 + 1) * 16];
                float4 w2 = w4[(d4 * 4 + 2) * 16];
                float4 w3 = w4[(d4 * 4 + 3) * 16];
                acc.x += hv.x * w0.x; acc.y += hv.x * w0.y; acc.z += hv.x * w0.z; acc.w += hv.x * w0.w;
                acc.x += hv.y * w1.x; acc.y += hv.y * w1.y; acc.z += hv.y * w1.z; acc.w += hv.y * w1.w;
                acc.x += hv.z * w2.x; acc.y += hv.z * w2.y; acc.z += hv.z * w2.z; acc.w += hv.z * w2.w;
                acc.x += hv.w * w3.x; acc.y += hv.w * w3.y; acc.z += hv.w * w3.z; acc.w += hv.w * w3.w;
            }
        }

        float4 hn;
        hn.x = tanhf(acc.x + xin.x);
        hn.y = tanhf(acc.y + xin.y);
        hn.z = tanhf(acc.z + xin.z);
        hn.w = tanhf(acc.w + xin.w);

        __stcg((float4*)(g_h + (size_t)((l + 1) & 1) * (BATCH * DIM)
                         + (size_t)grow * DIM + col0 + (c4 << 2)), hn);

        // ---- release: make h-stores GPU-visible, then publish step flag ----
        __threadfence();
        __syncthreads();
        if (tid == 0) stflag_rel(myflag, base + (unsigned)(l + 1));
    }
    // flags left at base+512: next launch reads them as its new base (no reset needed)
}

// ---------------- kernel 3: logits + softmax --------------------------------
// final h is in g_h[0] (step 511 writes buffer (511+1)&1 == 0).
__global__ __launch_bounds__(256) void softmax_kernel(
    const float* __restrict__ Wd,   // [512][20]
    const float* __restrict__ bd,   // [20]
    float* __restrict__ out)        // [256][20]
{
    int b    = blockIdx.x * 8 + (threadIdx.x >> 5);
    int lane = threadIdx.x & 31;
    if (b >= BATCH) return;

    const float* h = g_h + (size_t)b * DIM;

    float acc[NCLS];
    #pragma unroll
    for (int c = 0; c < NCLS; c++) acc[c] = 0.f;

    for (int d = lane; d < DIM; d += 32) {
        float hv = __ldcg(h + d);
        #pragma unroll
        for (int c = 0; c < NCLS; c++)
            acc[c] += hv * Wd[d * NCLS + c];
    }
    #pragma unroll
    for (int c = 0; c < NCLS; c++) {
        #pragma unroll
        for (int off = 16; off > 0; off >>= 1)
            acc[c] += __shfl_xor_sync(0xFFFFFFFFu, acc[c], off);
    }
    if (lane == 0) {
        float logit[NCLS];
        float m = -1e30f;
        #pragma unroll
        for (int c = 0; c < NCLS; c++) {
            logit[c] = acc[c] + bd[c];
            m = fmaxf(m, logit[c]);
        }
        float s = 0.f;
        #pragma unroll
        for (int c = 0; c < NCLS; c++) {
            logit[c] = expf(logit[c] - m);
            s += logit[c];
        }
        float inv = 1.0f / s;
        #pragma unroll
        for (int c = 0; c < NCLS; c++)
            out[b * NCLS + c] = logit[c] * inv;
    }
}

// ---------------- launch ----------------------------------------------------
extern "C" void kernel_launch(void* const* d_in, const int* in_sizes, int n_in,
                              void* d_out, int out_size)
{
    const int*   x   = (const int*)  d_in[0];
    const float* emb = (const float*)d_in[1];
    const float* Wx  = (const float*)d_in[2];
    const float* Wh  = (const float*)d_in[3];
    const float* b   = (const float*)d_in[4];
    const float* Wd  = (const float*)d_in[5];
    const float* bd  = (const float*)d_in[6];
    float* out = (float*)d_out;

    // 1) embW = emb @ Wx + b
    embw_gemm<<<dim3(DIM / 64, (VOCAB + 127) / 128), 256>>>(emb, Wx, b, VOCAB);

    // 2) persistent recurrence (128 CTAs, ~160KB dynamic smem, all resident)
    cudaFuncSetAttribute(rnn_recur, cudaFuncAttributeMaxDynamicSharedMemorySize,
                         RNN_SMEM_BYTES);
    rnn_recur<<<128, 256, RNN_SMEM_BYTES>>>(x, Wh);

    // 3) logits + softmax
    softmax_kernel<<<(BATCH + 7) / 8, 256>>>(Wd, bd, out);
}